// round 16
// baseline (speedup 1.0000x reference)
#include <cuda_runtime.h>
#include <cstdint>
#include <cstddef>

#define BATCH 32
#define SEQT  2048
#define INSZ  512
#define HID   512
#define G3    1536
#define NT    256
#define NGRP  8
#define GSZ2  32
typedef unsigned long long ull;

__device__ float g_xg[(size_t)SEQT * BATCH * G3];   // [t][b][3H]
__device__ float g_h[2][BATCH * HID];
__device__ unsigned g_flags[256][32];               // per-CTA step flag, 128B stride
__device__ unsigned g_bcount[NGRP][32];             // one-time init barrier (ends at 0)
__device__ unsigned g_bgen[NGRP][32];

__device__ __forceinline__ ull pk2(float x, float y) {
  ull r; asm("mov.b64 %0, {%1,%2};" : "=l"(r) : "f"(x), "f"(y)); return r;
}
__device__ __forceinline__ ull ffma2(ull a, ull b, ull c) {
  ull d; asm("fma.rn.f32x2 %0, %1, %2, %3;" : "=l"(d) : "l"(a), "l"(b), "l"(c)); return d;
}
__device__ __forceinline__ float2 upk2(ull v) {
  float x, y; asm("mov.b64 {%0,%1}, %2;" : "=f"(x), "=f"(y) : "l"(v));
  return make_float2(x, y);
}
__device__ __forceinline__ float sigmoid_f(float x) { return 1.f / (1.f + __expf(-x)); }
__device__ __forceinline__ float tanh_f(float x) {
  float e = __expf(-2.f * x); return (1.f - e) / (1.f + e);
}

// =============================================================
// Kernel A: x_gates GEMM — 128x64 tile, 2 CTAs/SM (16 warps)
// =============================================================
__global__ __launch_bounds__(256, 2) void gemm_xgates(
    const float* __restrict__ A, const float* __restrict__ Wih,
    const float* __restrict__ bih) {
  __shared__ ull As2[2][8][128];   // k-parity pairs, [kk][m]
  __shared__ ull Bs2[2][8][64];

  const int tid = threadIdx.x;
  const int m0 = blockIdx.y << 7, n0 = blockIdx.x << 6;
  const int tx = tid & 15, ty = tid >> 4;         // 16x16: ty rows, tx col-pairs
  const int lrowA = tid & 127, lkA = (tid >> 7) << 3;   // A loader
  const int lrowB = tid & 63,  lkB = (tid >> 6) << 2;   // B loader
  const int ty4 = ty * 4;

  const float* Ap = A + (size_t)(m0 + lrowA) * INSZ + lkA;
  const float* Bp = Wih + (size_t)(n0 + lrowB) * INSZ + lkB;

  ull acc[32];
#pragma unroll
  for (int i = 0; i < 32; i++) acc[i] = 0ull;

  float4 la0 = *(const float4*)(Ap), la1 = *(const float4*)(Ap + 4);
  float4 lb0 = *(const float4*)(Bp);
  {
    int kkA = lkA >> 1, kkB = lkB >> 1;
    As2[0][kkA + 0][lrowA] = pk2(la0.x, la0.y);
    As2[0][kkA + 1][lrowA] = pk2(la0.z, la0.w);
    As2[0][kkA + 2][lrowA] = pk2(la1.x, la1.y);
    As2[0][kkA + 3][lrowA] = pk2(la1.z, la1.w);
    Bs2[0][kkB + 0][lrowB] = pk2(lb0.x, lb0.y);
    Bs2[0][kkB + 1][lrowB] = pk2(lb0.z, lb0.w);
  }
  __syncthreads();

  for (int kt = 0; kt < 32; kt++) {
    const int cur = kt & 1, nxt = cur ^ 1;
    if (kt < 31) {
      Ap += 16; Bp += 16;
      la0 = *(const float4*)(Ap); la1 = *(const float4*)(Ap + 4);
      lb0 = *(const float4*)(Bp);
    }
#pragma unroll
    for (int kk = 0; kk < 8; kk++) {
      ulonglong2 aa0 = *(const ulonglong2*)&As2[cur][kk][ty4];
      ulonglong2 aa1 = *(const ulonglong2*)&As2[cur][kk][ty4 + 2];
      ulonglong2 aa2 = *(const ulonglong2*)&As2[cur][kk][64 + ty4];
      ulonglong2 aa3 = *(const ulonglong2*)&As2[cur][kk][64 + ty4 + 2];
      ulonglong2 bb0 = *(const ulonglong2*)&Bs2[cur][kk][tx * 2];
      ulonglong2 bb1 = *(const ulonglong2*)&Bs2[cur][kk][32 + tx * 2];
      ull a2[8] = {aa0.x, aa0.y, aa1.x, aa1.y, aa2.x, aa2.y, aa3.x, aa3.y};
      ull b2[4] = {bb0.x, bb0.y, bb1.x, bb1.y};
#pragma unroll
      for (int i = 0; i < 8; i++)
#pragma unroll
        for (int j = 0; j < 4; j++)
          acc[i * 4 + j] = ffma2(a2[i], b2[j], acc[i * 4 + j]);
    }
    if (kt < 31) {
      int kkA = lkA >> 1, kkB = lkB >> 1;
      As2[nxt][kkA + 0][lrowA] = pk2(la0.x, la0.y);
      As2[nxt][kkA + 1][lrowA] = pk2(la0.z, la0.w);
      As2[nxt][kkA + 2][lrowA] = pk2(la1.x, la1.y);
      As2[nxt][kkA + 3][lrowA] = pk2(la1.z, la1.w);
      Bs2[nxt][kkB + 0][lrowB] = pk2(lb0.x, lb0.y);
      Bs2[nxt][kkB + 1][lrowB] = pk2(lb0.z, lb0.w);
    }
    __syncthreads();
  }

  float2 bia0 = *(const float2*)(bih + n0 + tx * 2);
  float2 bia1 = *(const float2*)(bih + n0 + 32 + tx * 2);
#pragma unroll
  for (int i = 0; i < 8; i++) {
    int m = m0 + ((i < 4) ? (ty4 + i) : (64 + ty4 + i - 4));
    int b = m >> 11, t = m & 2047;
    float* orow = g_xg + ((size_t)t * BATCH + b) * G3 + n0;
    float2 p, o0, o1;
    p = upk2(acc[i * 4 + 0]); o0.x = p.x + p.y + bia0.x;
    p = upk2(acc[i * 4 + 1]); o0.y = p.x + p.y + bia0.y;
    p = upk2(acc[i * 4 + 2]); o1.x = p.x + p.y + bia1.x;
    p = upk2(acc[i * 4 + 3]); o1.y = p.x + p.y + bia1.y;
    *(float2*)(orow + tx * 2) = o0;
    *(float2*)(orow + 32 + tx * 2) = o1;
  }
}

// =============================================================
// Kernel B: persistent GRU scan — register reduce, per-producer poll
// 8 groups x 32 CTAs; group = 4 batches; CTA = 16 cols; warp = 6 rows
// smem: WS 96KB @0 | HS 8KB @98304 | bh @106496
// =============================================================
__device__ __forceinline__ void init_barrier(int grp) {
  __syncthreads();
  if (threadIdx.x == 0) {
    unsigned* cnt = &g_bcount[grp][0];
    unsigned* gen = &g_bgen[grp][0];
    unsigned g0;
    asm volatile("ld.acquire.gpu.global.u32 %0,[%1];" : "=r"(g0) : "l"(gen) : "memory");
    unsigned a;
    asm volatile("atom.add.acq_rel.gpu.global.u32 %0,[%1],1;" : "=r"(a) : "l"(cnt) : "memory");
    if (a == GSZ2 - 1) {
      asm volatile("st.relaxed.gpu.global.u32 [%0],0;" :: "l"(cnt) : "memory");
      unsigned tmp;
      asm volatile("atom.add.release.gpu.global.u32 %0,[%1],1;" : "=r"(tmp) : "l"(gen) : "memory");
    } else {
      unsigned cur;
      do {
        asm volatile("ld.acquire.gpu.global.u32 %0,[%1];" : "=r"(cur) : "l"(gen) : "memory");
      } while (cur == g0);
    }
  }
  __syncthreads();
}

#define SCAN_SMEM 106688

__global__ __launch_bounds__(NT, 2)
void gru_scan(const float* __restrict__ Whh, const float* __restrict__ bhh,
              const float* __restrict__ h0, float* __restrict__ out) {
  extern __shared__ char smem[];
  char* WS = smem;                      // 48 rows x 2048B, plain row-major
  char* HS = smem + 98304;              // [b][512 cols], plain row-major
  float* bh = (float*)(smem + 106496);  // [48] = [jj*3+g]

  const int tid = threadIdx.x;
  const int grp = (int)blockIdx.x >> 5;
  const int cid = (int)blockIdx.x & 31;
  const int j0  = cid << 4;
  const int b0g = grp << 2;
  const int w = tid >> 5, lane = tid & 31;

  for (int idx = tid; idx < 48 * 128; idx += NT) {
    int R = idx >> 7, c4 = idx & 127;
    int jj = R / 3, g = R - jj * 3;
    *(float4*)(WS + R * 2048 + c4 * 16) =
        *(const float4*)(Whh + (size_t)(g * HID + j0 + jj) * HID + (c4 << 2));
  }
  if (tid < 48) {
    int jj = tid / 3, g = tid - jj * 3;
    bh[tid] = bhh[g * HID + j0 + jj];
  }
  if (tid == 0) g_flags[blockIdx.x][0] = 0u;
  init_barrier(grp);

  // staging assignment: this thread stages float4 #f of producer p
  const int p_own = tid & 31;           // producer rank this thread tracks
  const int f_base = tid >> 5;          // 0..7; f = f_base + i*8, i=0..1
  // gate role (lanes 0..7): jl in {0,1}, bq in {0..3}
  const int jl = lane >> 2, bq = lane & 3;
  const int gcol = j0 + w * 2 + jl;

  for (int t = 0; t < SEQT; t++) {
    const float* hsrc = (t == 0) ? h0 : &g_h[t & 1][0];
    float* hn = &g_h[(t + 1) & 1][0];

    // xg prefetch for gate lanes
    float xr = 0.f, xz = 0.f, xn = 0.f;
    if (lane < 8) {
      const float* xgp = g_xg + ((size_t)t * BATCH + (b0g + bq)) * G3 + gcol;
      xr = __ldcg(xgp); xz = __ldcg(xgp + HID); xn = __ldcg(xgp + 2 * HID);
    }

    // per-producer acquire: poll exactly the flag of the producer we stage
    if (t > 0) {
      const unsigned* fp = &g_flags[grp * 32 + p_own][0];
      unsigned v;
      do {
        asm volatile("ld.acquire.gpu.global.u32 %0,[%1];" : "=r"(v) : "l"(fp) : "memory");
      } while (v < (unsigned)t);
    }

    // stage ONLY producer p_own's 16 float4s (its 16 cols x 4 batches)
#pragma unroll
    for (int i = 0; i < 2; i++) {
      int f = f_base + i * 8;            // 0..15
      int b_r = f >> 2, c4l = f & 3;
      const float* src = hsrc + (size_t)(b0g + b_r) * HID + p_own * 16 + c4l * 4;
      float4 v;
      asm volatile("ld.global.cg.v4.f32 {%0,%1,%2,%3},[%4];"
                   : "=f"(v.x), "=f"(v.y), "=f"(v.z), "=f"(v.w) : "l"(src));
      *(float4*)(HS + b_r * 2048 + p_own * 64 + c4l * 16) = v;
    }
    __syncthreads();

    // compute: 6 rows x 4 batches x 16 k per lane, k-chunked
    ull acc[24];
#pragma unroll
    for (int c = 0; c < 24; c++) acc[c] = 0ull;
#pragma unroll
    for (int i = 0; i < 4; i++) {
      const char* hb = HS + i * 512 + lane * 16;
      ull h0r[4], h1r[4];
#pragma unroll
      for (int b = 0; b < 4; b++) {
        ulonglong2 u = *(const ulonglong2*)(hb + b * 2048);
        h0r[b] = u.x; h1r[b] = u.y;
      }
      const char* wb = WS + (w * 6) * 2048 + i * 512 + lane * 16;
#pragma unroll
      for (int rl = 0; rl < 6; rl++) {
        ulonglong2 wv = *(const ulonglong2*)(wb + rl * 2048);
#pragma unroll
        for (int b = 0; b < 4; b++) {
          ull s = acc[rl * 4 + b];
          s = ffma2(wv.x, h0r[b], s);
          s = ffma2(wv.y, h1r[b], s);
          acc[rl * 4 + b] = s;
        }
      }
    }

    // full butterfly; route (rl,b) sum to gate lane (rl/3)*4+b, gate reg by rl%3
    float sr = 0.f, sz = 0.f, sn = 0.f;
#pragma unroll
    for (int c = 0; c < 24; c++) {
      float2 pc = upk2(acc[c]);
      float v = pc.x + pc.y;
      v += __shfl_xor_sync(0xffffffffu, v, 16);
      v += __shfl_xor_sync(0xffffffffu, v, 8);
      v += __shfl_xor_sync(0xffffffffu, v, 4);
      v += __shfl_xor_sync(0xffffffffu, v, 2);
      v += __shfl_xor_sync(0xffffffffu, v, 1);
      const int tgt = (c / 12) * 4 + (c & 3);
      const int g = (c % 12) >> 2;
      if (lane == tgt) {
        if (g == 0) sr = v;
        else if (g == 1) sz = v;
        else sn = v;
      }
    }

    // gates (lanes 0..7 of each warp)
    float hnew = 0.f;
    if (lane < 8) {
      float hprev = *(const float*)(HS + bq * 2048 + gcol * 4);
      int jj_o = w * 2 + jl;
      float rg = sigmoid_f(xr + sr + bh[jj_o * 3 + 0]);
      float zg = sigmoid_f(xz + sz + bh[jj_o * 3 + 1]);
      float ng = tanh_f(xn + rg * (sn + bh[jj_o * 3 + 2]));
      hnew = ng + zg * (hprev - ng);
      hn[(b0g + bq) * HID + gcol] = hnew;
    }
    __syncthreads();   // all h stores done before release
    if (tid == 0) {
      unsigned* fp = &g_flags[blockIdx.x][0];
      asm volatile("st.release.gpu.global.u32 [%0],%1;" :: "l"(fp), "r"((unsigned)(t + 1)) : "memory");
    }
    // out-write off the critical path
    if (lane < 8) {
      out[((size_t)(b0g + bq) * SEQT + t) * HID + gcol] = hnew;
    }
  }
}

extern "C" void kernel_launch(void* const* d_in, const int* in_sizes, int n_in,
                              void* d_out, int out_size) {
  (void)in_sizes; (void)n_in; (void)out_size;
  const float* input = (const float*)d_in[0];
  const float* h0    = (const float*)d_in[1];
  const float* wih   = (const float*)d_in[2];
  const float* whh   = (const float*)d_in[3];
  const float* bih   = (const float*)d_in[4];
  const float* bhh   = (const float*)d_in[5];
  float* out = (float*)d_out;

  cudaFuncSetAttribute(gru_scan, cudaFuncAttributeMaxDynamicSharedMemorySize, SCAN_SMEM);

  dim3 gA(G3 / 64, (BATCH * SEQT) / 128);   // 24 x 512 blocks of 128x64
  gemm_xgates<<<gA, 256>>>(input, wih, bih);
  gru_scan<<<NGRP * GSZ2, NT, SCAN_SMEM>>>(whh, bhh, h0, out);
}

// round 17
// speedup vs baseline: 1.3384x; 1.3384x over previous
#include <cuda_runtime.h>
#include <cstdint>
#include <cstddef>

#define BATCH 32
#define SEQT  2048
#define INSZ  512
#define HID   512
#define G3    1536
#define NT    256
#define NGRP  8
#define GSZ2  16
typedef unsigned long long ull;

__device__ float g_xg[(size_t)SEQT * BATCH * G3];   // [t][b][3H]
__device__ float g_h[2][BATCH * HID];
__device__ unsigned g_flags[128][32];               // per-CTA step flag, 128B stride
__device__ unsigned g_bcount[NGRP][32];             // one-time init barrier (ends at 0)
__device__ unsigned g_bgen[NGRP][32];

// ---- packed f32x2 helpers ----
__device__ __forceinline__ ull pk2(float x, float y) {
  ull r; asm("mov.b64 %0, {%1,%2};" : "=l"(r) : "f"(x), "f"(y)); return r;
}
__device__ __forceinline__ ull ffma2(ull a, ull b, ull c) {
  ull d; asm("fma.rn.f32x2 %0, %1, %2, %3;" : "=l"(d) : "l"(a), "l"(b), "l"(c)); return d;
}
__device__ __forceinline__ float2 upk2(ull v) {
  float x, y; asm("mov.b64 {%0,%1}, %2;" : "=f"(x), "=f"(y) : "l"(v));
  return make_float2(x, y);
}
__device__ __forceinline__ float sigmoid_f(float x) { return 1.f / (1.f + __expf(-x)); }
__device__ __forceinline__ float tanh_f(float x) {
  float e = __expf(-2.f * x); return (1.f - e) / (1.f + e);
}

// =============================================================
// Kernel A: x_gates GEMM — 128x64 tile, 2 CTAs/SM (16 warps)
// (correctness-proven in R16; now measured in isolation)
// =============================================================
__global__ __launch_bounds__(256, 2) void gemm_xgates(
    const float* __restrict__ A, const float* __restrict__ Wih,
    const float* __restrict__ bih) {
  __shared__ ull As2[2][8][128];   // k-parity pairs, [kk][m]
  __shared__ ull Bs2[2][8][64];

  const int tid = threadIdx.x;
  const int m0 = blockIdx.y << 7, n0 = blockIdx.x << 6;
  const int tx = tid & 15, ty = tid >> 4;
  const int lrowA = tid & 127, lkA = (tid >> 7) << 3;
  const int lrowB = tid & 63,  lkB = (tid >> 6) << 2;
  const int ty4 = ty * 4;

  const float* Ap = A + (size_t)(m0 + lrowA) * INSZ + lkA;
  const float* Bp = Wih + (size_t)(n0 + lrowB) * INSZ + lkB;

  ull acc[32];
#pragma unroll
  for (int i = 0; i < 32; i++) acc[i] = 0ull;

  float4 la0 = *(const float4*)(Ap), la1 = *(const float4*)(Ap + 4);
  float4 lb0 = *(const float4*)(Bp);
  {
    int kkA = lkA >> 1, kkB = lkB >> 1;
    As2[0][kkA + 0][lrowA] = pk2(la0.x, la0.y);
    As2[0][kkA + 1][lrowA] = pk2(la0.z, la0.w);
    As2[0][kkA + 2][lrowA] = pk2(la1.x, la1.y);
    As2[0][kkA + 3][lrowA] = pk2(la1.z, la1.w);
    Bs2[0][kkB + 0][lrowB] = pk2(lb0.x, lb0.y);
    Bs2[0][kkB + 1][lrowB] = pk2(lb0.z, lb0.w);
  }
  __syncthreads();

  for (int kt = 0; kt < 32; kt++) {
    const int cur = kt & 1, nxt = cur ^ 1;
    if (kt < 31) {
      Ap += 16; Bp += 16;
      la0 = *(const float4*)(Ap); la1 = *(const float4*)(Ap + 4);
      lb0 = *(const float4*)(Bp);
    }
#pragma unroll
    for (int kk = 0; kk < 8; kk++) {
      ulonglong2 aa0 = *(const ulonglong2*)&As2[cur][kk][ty4];
      ulonglong2 aa1 = *(const ulonglong2*)&As2[cur][kk][ty4 + 2];
      ulonglong2 aa2 = *(const ulonglong2*)&As2[cur][kk][64 + ty4];
      ulonglong2 aa3 = *(const ulonglong2*)&As2[cur][kk][64 + ty4 + 2];
      ulonglong2 bb0 = *(const ulonglong2*)&Bs2[cur][kk][tx * 2];
      ulonglong2 bb1 = *(const ulonglong2*)&Bs2[cur][kk][32 + tx * 2];
      ull a2[8] = {aa0.x, aa0.y, aa1.x, aa1.y, aa2.x, aa2.y, aa3.x, aa3.y};
      ull b2[4] = {bb0.x, bb0.y, bb1.x, bb1.y};
#pragma unroll
      for (int i = 0; i < 8; i++)
#pragma unroll
        for (int j = 0; j < 4; j++)
          acc[i * 4 + j] = ffma2(a2[i], b2[j], acc[i * 4 + j]);
    }
    if (kt < 31) {
      int kkA = lkA >> 1, kkB = lkB >> 1;
      As2[nxt][kkA + 0][lrowA] = pk2(la0.x, la0.y);
      As2[nxt][kkA + 1][lrowA] = pk2(la0.z, la0.w);
      As2[nxt][kkA + 2][lrowA] = pk2(la1.x, la1.y);
      As2[nxt][kkA + 3][lrowA] = pk2(la1.z, la1.w);
      Bs2[nxt][kkB + 0][lrowB] = pk2(lb0.x, lb0.y);
      Bs2[nxt][kkB + 1][lrowB] = pk2(lb0.z, lb0.w);
    }
    __syncthreads();
  }

  float2 bia0 = *(const float2*)(bih + n0 + tx * 2);
  float2 bia1 = *(const float2*)(bih + n0 + 32 + tx * 2);
#pragma unroll
  for (int i = 0; i < 8; i++) {
    int m = m0 + ((i < 4) ? (ty4 + i) : (64 + ty4 + i - 4));
    int b = m >> 11, t = m & 2047;
    float* orow = g_xg + ((size_t)t * BATCH + b) * G3 + n0;
    float2 p, o0, o1;
    p = upk2(acc[i * 4 + 0]); o0.x = p.x + p.y + bia0.x;
    p = upk2(acc[i * 4 + 1]); o0.y = p.x + p.y + bia0.y;
    p = upk2(acc[i * 4 + 2]); o1.x = p.x + p.y + bia1.x;
    p = upk2(acc[i * 4 + 3]); o1.y = p.x + p.y + bia1.y;
    *(float2*)(orow + tx * 2) = o0;
    *(float2*)(orow + 32 + tx * 2) = o1;
  }
}

// =============================================================
// Kernel B: persistent GRU scan — R14 best-known source, verbatim
// 8 groups x 16 CTAs; group = 4 batches; CTA = 32 cols; warp = 12 rows
// Lane owns k in {4*lane + 128*i, i=0..3}
// red layout: OFF(b,w,rl,p) = b*800 + w*100 + rl*8 + p   (padded stride)
// smem: WS 192KB @0 | HS 8KB @196608 | red 12.8KB @204800 | bh @217600
// =============================================================
__device__ __forceinline__ void init_barrier(int grp) {
  __syncthreads();
  if (threadIdx.x == 0) {
    unsigned* cnt = &g_bcount[grp][0];
    unsigned* gen = &g_bgen[grp][0];
    unsigned g0;
    asm volatile("ld.acquire.gpu.global.u32 %0,[%1];" : "=r"(g0) : "l"(gen) : "memory");
    unsigned a;
    asm volatile("atom.add.acq_rel.gpu.global.u32 %0,[%1],1;" : "=r"(a) : "l"(cnt) : "memory");
    if (a == GSZ2 - 1) {
      asm volatile("st.relaxed.gpu.global.u32 [%0],0;" :: "l"(cnt) : "memory");
      unsigned tmp;
      asm volatile("atom.add.release.gpu.global.u32 %0,[%1],1;" : "=r"(tmp) : "l"(gen) : "memory");
    } else {
      unsigned cur;
      do {
        asm volatile("ld.acquire.gpu.global.u32 %0,[%1];" : "=r"(cur) : "l"(gen) : "memory");
      } while (cur == g0);
    }
  }
  __syncthreads();
}

#define SCAN_SMEM 217984

__global__ __launch_bounds__(NT, 1)
void gru_scan(const float* __restrict__ Whh, const float* __restrict__ bhh,
              const float* __restrict__ h0, float* __restrict__ out) {
  extern __shared__ char smem[];
  char* WS = smem;                      // 96 rows x 2048B, plain row-major
  char* HS = smem + 196608;             // [b][512 cols], plain row-major, 8KB
  float* red = (float*)(smem + 204800); // [b][w][rl][8], w-stride 100 floats
  float* bh  = (float*)(smem + 217600); // [96] = [jj*3+g]

  const int tid = threadIdx.x;
  const int grp = (int)blockIdx.x >> 4;
  const int cid = (int)blockIdx.x & 15;
  const int j0  = cid << 5;
  const int b0g = grp << 2;
  const int w = tid >> 5, lane = tid & 31;

  for (int idx = tid; idx < 96 * 128; idx += NT) {
    int R = idx >> 7, c4 = idx & 127;
    int jj = R / 3, g = R - jj * 3;
    *(float4*)(WS + R * 2048 + c4 * 16) =
        *(const float4*)(Whh + (size_t)(g * HID + j0 + jj) * HID + (c4 << 2));
  }
  if (tid < 96) {
    int jj = tid / 3, g = tid - jj * 3;
    bh[tid] = bhh[g * HID + j0 + jj];
  }
  if (tid == 0) g_flags[blockIdx.x][0] = 0u;
  init_barrier(grp);

  const int b_o = tid >> 5, jj_o = tid & 31;

  for (int t = 0; t < SEQT; t++) {
    const float* hsrc = (t == 0) ? h0 : &g_h[t & 1][0];
    float* hn = &g_h[(t + 1) & 1][0];

    float xr = 0.f, xz = 0.f, xn = 0.f;
    if (tid < 128) {
      const float* xgp = g_xg + ((size_t)t * BATCH + (b0g + b_o)) * G3 + j0 + jj_o;
      xr = __ldcg(xgp); xz = __ldcg(xgp + HID); xn = __ldcg(xgp + 2 * HID);
    }

    if (t > 0) {
      if (tid < 16) {
        const unsigned* fp = &g_flags[grp * 16 + tid][0];
        unsigned v;
        do {
          asm volatile("ld.acquire.gpu.global.u32 %0,[%1];" : "=r"(v) : "l"(fp) : "memory");
        } while (v < (unsigned)t);
      }
      __syncthreads();
    }

#pragma unroll
    for (int i = 0; i < 2; i++) {
      int idx = i * NT + tid;
      const float* src = hsrc + (size_t)b0g * HID + ((size_t)idx << 2);
      float4 v;
      asm volatile("ld.global.cg.v4.f32 {%0,%1,%2,%3},[%4];"
                   : "=f"(v.x), "=f"(v.y), "=f"(v.z), "=f"(v.w) : "l"(src));
      *(float4*)(HS + idx * 16) = v;
    }
    __syncthreads();

    ull hreg[4][8];
#pragma unroll
    for (int b = 0; b < 4; b++) {
      const char* hb = HS + b * 2048 + lane * 16;
#pragma unroll
      for (int i = 0; i < 4; i++) {
        ulonglong2 u = *(const ulonglong2*)(hb + i * 512);
        hreg[b][i * 2] = u.x; hreg[b][i * 2 + 1] = u.y;
      }
    }
    float hprev = 0.f;
    if (tid < 128) hprev = *(const float*)(HS + b_o * 2048 + (j0 + jj_o) * 4);

    ull acc[48];
#pragma unroll
    for (int c = 0; c < 48; c++) acc[c] = 0ull;
#pragma unroll
    for (int rl = 0; rl < 12; rl++) {
      const char* wrow = WS + (w * 12 + rl) * 2048 + lane * 16;
      ull wu[8];
#pragma unroll
      for (int i = 0; i < 4; i++) {
        ulonglong2 u = *(const ulonglong2*)(wrow + i * 512);
        wu[i * 2] = u.x; wu[i * 2 + 1] = u.y;
      }
#pragma unroll
      for (int b = 0; b < 4; b++) {
        ull s = acc[rl * 4 + b];
#pragma unroll
        for (int u = 0; u < 8; u++) s = ffma2(wu[u], hreg[b][u], s);
        acc[rl * 4 + b] = s;
      }
    }

#pragma unroll
    for (int c = 0; c < 48; c++) {
      float2 p = upk2(acc[c]);
      float v = p.x + p.y;
      v += __shfl_xor_sync(0xffffffffu, v, 16);
      v += __shfl_xor_sync(0xffffffffu, v, 8);
      if (lane < 8) {
        int rl = c >> 2, b = c & 3;
        red[b * 800 + w * 100 + rl * 8 + lane] = v;
      }
    }
    __syncthreads();

    if (tid < 128) {
      int wj = jj_o >> 2, jl = jj_o & 3;
      const float4* rp = (const float4*)(red + b_o * 800 + wj * 100 + jl * 24);
      float4 q0 = rp[0], q1 = rp[1];
      float4 q2 = rp[2], q3 = rp[3];
      float4 q4 = rp[4], q5 = rp[5];
      float sr = (q0.x + q0.y) + (q0.z + q0.w) + (q1.x + q1.y) + (q1.z + q1.w);
      float sz = (q2.x + q2.y) + (q2.z + q2.w) + (q3.x + q3.y) + (q3.z + q3.w);
      float sn = (q4.x + q4.y) + (q4.z + q4.w) + (q5.x + q5.y) + (q5.z + q5.w);
      float rg = sigmoid_f(xr + sr + bh[jj_o * 3 + 0]);
      float zg = sigmoid_f(xz + sz + bh[jj_o * 3 + 1]);
      float ng = tanh_f(xn + rg * (sn + bh[jj_o * 3 + 2]));
      float hnew = ng + zg * (hprev - ng);
      hn[(b0g + b_o) * HID + j0 + jj_o] = hnew;
      out[((size_t)(b0g + b_o) * SEQT + t) * HID + j0 + jj_o] = hnew;
    }
    __syncthreads();
    if (tid == 0) {
      unsigned* fp = &g_flags[blockIdx.x][0];
      asm volatile("st.release.gpu.global.u32 [%0],%1;" :: "l"(fp), "r"((unsigned)(t + 1)) : "memory");
    }
  }
}

extern "C" void kernel_launch(void* const* d_in, const int* in_sizes, int n_in,
                              void* d_out, int out_size) {
  (void)in_sizes; (void)n_in; (void)out_size;
  const float* input = (const float*)d_in[0];
  const float* h0    = (const float*)d_in[1];
  const float* wih   = (const float*)d_in[2];
  const float* whh   = (const float*)d_in[3];
  const float* bih   = (const float*)d_in[4];
  const float* bhh   = (const float*)d_in[5];
  float* out = (float*)d_out;

  cudaFuncSetAttribute(gru_scan, cudaFuncAttributeMaxDynamicSharedMemorySize, SCAN_SMEM);

  dim3 gA(G3 / 64, (BATCH * SEQT) / 128);   // 24 x 512 blocks of 128x64
  gemm_xgates<<<gA, 256>>>(input, wih, bih);
  gru_scan<<<NGRP * GSZ2, NT, SCAN_SMEM>>>(whh, bhh, h0, out);
}